// round 15
// baseline (speedup 1.0000x reference)
#include <cuda_runtime.h>
#include <cuda_fp16.h>
#include <math.h>
#include <stdint.h>

// Problem constants
#define LNUM 4
#define NB   8
#define Bsz  16
#define Ssz  512
#define Dsz  512
#define Msz  (Bsz * Ssz)          // 8192
#define BSD  (Bsz * Ssz * Dsz)

#define NCHUNK 32
#define ROWS_PER_CHUNK (Ssz / NCHUNK)   // 16

// ---------------- device scratch ----------------
__device__ float  g_c[BSD];
__device__ float  g_b[BSD];
__device__ __half g_xnh_c[BSD];
__device__ __half g_xnh_b[BSD];
__device__ __half g_h1h_c[Bsz * Ssz * 2 * Dsz];
__device__ __half g_h1h_b[BSD];
__device__ __half g_cmir[BSD];
__device__ __half g_bmir[BSD];
__device__ float  g_mean_c[2 * Bsz * Dsz];
__device__ float  g_mean_b[2 * Bsz * Dsz];
__device__ float  g_part_c[Bsz * NCHUNK * Dsz];
__device__ float  g_part_b[Bsz * NCHUNK * Dsz];
__device__ int    g_top_c[2];
__device__ int    g_top_b[2];
__device__ __half g_cw1T[4 * 8 * 1024 * 512];
__device__ __half g_cw2T[4 * 8 * 512 * 1024];
__device__ __half g_bw1T[4 * 8 * 512 * 512];
__device__ __half g_bw2T[4 * 8 * 512 * 512];
__device__ __half g_wcrT[512 * 1024];

// ---------------- helpers ----------------
__device__ __forceinline__ uint32_t smem_u32(const void* p) {
    uint32_t a;
    asm("{ .reg .u64 t; cvta.to.shared.u64 t, %1; cvt.u32.u64 %0, t; }" : "=r"(a) : "l"(p));
    return a;
}
__device__ __forceinline__ void cp_async16(uint32_t saddr, const void* gaddr) {
    asm volatile("cp.async.cg.shared.global [%0], [%1], 16;" :: "r"(saddr), "l"(gaddr) : "memory");
}
__device__ __forceinline__ void cp_commit() {
    asm volatile("cp.async.commit_group;" ::: "memory");
}
template <int N>
__device__ __forceinline__ void cp_wait() {
    asm volatile("cp.async.wait_group %0;" :: "n"(N) : "memory");
}
__device__ __forceinline__ void ldm_x4(uint32_t* r, uint32_t addr) {
    asm volatile("ldmatrix.sync.aligned.m8n8.x4.shared.b16 {%0,%1,%2,%3}, [%4];"
        : "=r"(r[0]), "=r"(r[1]), "=r"(r[2]), "=r"(r[3]) : "r"(addr));
}
__device__ __forceinline__ void mma_f16(float* c, const uint32_t* a, const uint32_t* b) {
    asm volatile(
        "mma.sync.aligned.m16n8k16.row.col.f32.f16.f16.f32 "
        "{%0,%1,%2,%3}, {%4,%5,%6,%7}, {%8,%9}, {%0,%1,%2,%3};"
        : "+f"(c[0]), "+f"(c[1]), "+f"(c[2]), "+f"(c[3])
        : "r"(a[0]), "r"(a[1]), "r"(a[2]), "r"(a[3]), "r"(b[0]), "r"(b[1]));
}
__device__ __forceinline__ float warp_sum(float v) {
#pragma unroll
    for (int o = 16; o > 0; o >>= 1) v += __shfl_xor_sync(0xffffffffu, v, o);
    return v;
}

// ---------------- LN body (shared by standalone + fused kernels) ----------------
__device__ __forceinline__ void ln_body(int row, int tid256,
                                        const float* __restrict__ x, __half* __restrict__ xn,
                                        const float* __restrict__ gg_, const float* __restrict__ bb_) {
    int lane = tid256 & 31;
    const float4* xr = (const float4*)(x + (size_t)row * Dsz);
    float4 v[4];
    float s = 0.f;
#pragma unroll
    for (int q = 0; q < 4; q++) {
        v[q] = xr[lane + q * 32];
        s += v[q].x + v[q].y + v[q].z + v[q].w;
    }
    float mu = warp_sum(s) * (1.f / Dsz);
    float ss = 0.f;
#pragma unroll
    for (int q = 0; q < 4; q++) {
        float a = v[q].x - mu, b = v[q].y - mu, c = v[q].z - mu, d = v[q].w - mu;
        ss += a * a + b * b + c * c + d * d;
    }
    float r = rsqrtf(warp_sum(ss) * (1.f / Dsz) + 1e-5f);
    const float4* gg = (const float4*)gg_;
    const float4* bb = (const float4*)bb_;
#pragma unroll
    for (int q = 0; q < 4; q++) {
        int c4 = lane + q * 32;
        float4 g = gg[c4], be = bb[c4];
        float o0 = (v[q].x - mu) * r * g.x + be.x;
        float o1 = (v[q].y - mu) * r * g.y + be.y;
        float o2 = (v[q].z - mu) * r * g.z + be.z;
        float o3 = (v[q].w - mu) * r * g.w + be.w;
        __half2 h0 = __floats2half2_rn(o0, o1);
        __half2 h1 = __floats2half2_rn(o2, o3);
        uint2 pk = make_uint2(*(uint32_t*)&h0, *(uint32_t*)&h1);
        *(uint2*)(xn + (size_t)row * Dsz + c4 * 4) = pk;
    }
}

// ---------------- small kernels ----------------
__global__ void colmean_partial_kernel(const float* __restrict__ x, float* __restrict__ part) {
    int b = blockIdx.x;
    int s = blockIdx.y;
    int d = threadIdx.x;
    const float* p = x + ((size_t)b * Ssz + (size_t)s * ROWS_PER_CHUNK) * Dsz + d;
    float sum = 0.f;
#pragma unroll
    for (int t = 0; t < ROWS_PER_CHUNK; t++) sum += p[(size_t)t * Dsz];
    part[((size_t)b * NCHUNK + s) * Dsz + d] = sum;
}

__global__ void colmean_finish_route_kernel(const float* __restrict__ part,
                                            float* __restrict__ mean,
                                            const float* __restrict__ wsel,
                                            const float* __restrict__ bsel,
                                            int* __restrict__ top) {
    __shared__ float smean[Dsz];
    __shared__ float adj[NB];
    int b = blockIdx.x;
    int d = threadIdx.x;
    const float* pp = part + (size_t)b * NCHUNK * Dsz + d;
    float s = 0.f;
#pragma unroll
    for (int t = 0; t < NCHUNK; t++) s += pp[(size_t)t * Dsz];
    float m = s * (1.0f / Ssz);
    mean[b * Dsz + d] = m;
    if (b == 0) {
        smean[d] = m;
        __syncthreads();
        if (d < 256) {
            int lane = d & 31, w = d >> 5;
            float acc = 0.f;
            for (int k = lane; k < Dsz; k += 32) acc += smean[k] * wsel[k * NB + w];
#pragma unroll
            for (int o = 16; o > 0; o >>= 1) acc += __shfl_down_sync(0xffffffffu, acc, o);
            if (lane == 0) {
                float sc = 1.f / (1.f + expf(-(acc + bsel[w])));
                adj[w] = sc * 0.7f + 0.15f;
            }
        }
        __syncthreads();
        if (d == 0) {
            int i1 = 0; float v1 = adj[0];
            for (int n = 1; n < NB; n++) if (adj[n] > v1) { v1 = adj[n]; i1 = n; }
            int i2 = -1; float v2 = -1e30f;
            for (int n = 0; n < NB; n++) if (n != i1 && adj[n] > v2) { v2 = adj[n]; i2 = n; }
            top[0] = i1; top[1] = i2;
        }
    }
}

// standalone LN (for j=1, depends on preceding G2)
__global__ void ln_kernel(const float* __restrict__ x, __half* __restrict__ xn,
                          const float* __restrict__ lng, const float* __restrict__ lnb,
                          const int* __restrict__ top, int jsel) {
    int i = top[jsel];
    int row = blockIdx.x * 8 + (threadIdx.x >> 5);
    ln_body(row, threadIdx.x, x, xn, lng + (size_t)i * Dsz, lnb + (size_t)i * Dsz);
}

// single-matrix transpose (cross weights)
__global__ void transpose_h_kernel(const float* __restrict__ W, __half* __restrict__ WT,
                                   int K, int N, const int* __restrict__ top) {
    __shared__ float tile[32][33];
    int ii = top ? top[blockIdx.z] : (int)blockIdx.z;
    const float* Wz = W + (size_t)ii * K * N;
    __half* Tz = WT + (size_t)ii * K * N;
    int x = blockIdx.x * 32 + threadIdx.x;
    int y0 = blockIdx.y * 32;
#pragma unroll
    for (int j = 0; j < 4; j++)
        tile[threadIdx.y + j * 8][threadIdx.x] = Wz[(size_t)(y0 + threadIdx.y + j * 8) * N + x];
    __syncthreads();
    int x2 = blockIdx.y * 32 + threadIdx.x;
    int y2 = blockIdx.x * 32;
#pragma unroll
    for (int j = 0; j < 4; j++)
        Tz[(size_t)(y2 + threadIdx.y + j * 8) * K + x2] = __float2half_rn(tile[threadIdx.x][threadIdx.y + j * 8]);
}

// FUSED per-layer head: routed transposes (w1+w2, both blocks) + LayerNorm(j=0), one launch.
// Blocks [0, nTrans): transpose, decoded as bx = v%tgx, by = (v/tgx)%tgy, bz = v/(tgx*tgy).
// Blocks [nTrans, nTrans + Msz/8): LN j=0 with top[0].
__global__ void head_ln_trans_kernel(
    const float* __restrict__ W1, __half* __restrict__ WT1, int K1, int N1,
    const float* __restrict__ W2, __half* __restrict__ WT2, int K2, int N2,
    const int* __restrict__ top, int nTrans, int tgx, int tgy,
    const float* __restrict__ x, __half* __restrict__ xn,
    const float* __restrict__ lng, const float* __restrict__ lnb)
{
    int v = blockIdx.x;
    int tid = threadIdx.x;
    if (v < nTrans) {
        __shared__ float tile[32][33];
        int bx = v % tgx;
        int by = (v / tgx) % tgy;
        int bz = v / (tgx * tgy);
        int tx = tid & 31, ty = tid >> 5;
        int msel = bz >> 1, blk = bz & 1;
        const float* W = msel ? W2 : W1;
        __half* WT = msel ? WT2 : WT1;
        int K = msel ? K2 : K1, N = msel ? N2 : N1;
        if (bx * 32 >= N || by * 32 >= K) return;
        int ii = top[blk];
        const float* Wz = W + (size_t)ii * K * N;
        __half* Tz = WT + (size_t)ii * K * N;
        int gx = bx * 32 + tx;
        int y0 = by * 32;
#pragma unroll
        for (int j = 0; j < 4; j++)
            tile[ty + j * 8][tx] = Wz[(size_t)(y0 + ty + j * 8) * N + gx];
        __syncthreads();
        int x2 = by * 32 + tx;
        int y2 = bx * 32;
#pragma unroll
        for (int j = 0; j < 4; j++)
            Tz[(size_t)(y2 + ty + j * 8) * K + x2] = __float2half_rn(tile[tx][ty + j * 8]);
    } else {
        int i = top[0];
        int row = (v - nTrans) * 8 + (tid >> 5);
        ln_body(row, tid, x, xn, lng + (size_t)i * Dsz, lnb + (size_t)i * Dsz);
    }
}

// ---------------- fp16 mma.sync GEMM: 128x128 tile, BK=64, 3-stage, single barrier ----------------
#define GEPI_GELU  0
#define GEPI_TANH  1
#define GEPI_BLOCK 2
#define GEPI_BIAS  3

#define KPADH 72
#define TILEH (128 * KPADH)
#define NSTAGE 3
#define MMA_SMEM_BYTES (NSTAGE * 2 * TILEH * 2)   // 110592 B

template <int EPI, bool CONCAT>
__global__ void __launch_bounds__(256, 2) mma_gemm(
    const __half* __restrict__ A, const __half* __restrict__ A2,
    const __half* __restrict__ BT, const float* __restrict__ bias,
    void* __restrict__ Cv, const float* __restrict__ oldC,
    __half* __restrict__ mirror, float* __restrict__ outDup,
    int M, int N, int K,
    const float* __restrict__ gate, const float* __restrict__ torsion,
    const float* __restrict__ meanOther,
    const int* __restrict__ top, int jsel)
{
    extern __shared__ __half smh[];

    int tid = threadIdx.x;
    int wid = tid >> 5, lane = tid & 31;
    int g = lane >> 2, t = lane & 3;
    int lr = lane & 7, seg = lane >> 3;
    int wm = wid & 3, wn = wid >> 2;
    int bm = blockIdx.y * 128;
    int bn = blockIdx.x * 128;

    int ii = 0;
    if (top) ii = top[jsel];
    const __half* Bp  = BT + (size_t)ii * K * N + (size_t)bn * K;
    const float*  bia = bias + (size_t)ii * N;

    uint32_t sbase = smem_u32(smh);

    auto load_tile = [&](int c) {
        int st = c % NSTAGE;
        int k0 = c << 6;
        uint32_t sAa = sbase + (uint32_t)(st * 2 * TILEH) * 2;
        uint32_t sBa = sAa + (uint32_t)TILEH * 2;
#pragma unroll
        for (int i = 0; i < 4; i++) {
            int idx = i * 256 + tid;
            int row = idx >> 3;
            int ch  = (idx & 7) * 8;
            const __half* gsrc;
            if (CONCAT) {
                int kk = k0 + ch;
                gsrc = (kk < 512) ? (A + (size_t)(bm + row) * 512 + kk)
                                  : (A2 + (size_t)(bm + row) * 512 + (kk - 512));
            } else {
                gsrc = A + (size_t)(bm + row) * K + k0 + ch;
            }
            cp_async16(sAa + (uint32_t)(row * KPADH + ch) * 2, gsrc);
            cp_async16(sBa + (uint32_t)(row * KPADH + ch) * 2, Bp + (size_t)row * K + k0 + ch);
        }
        cp_commit();
    };

    float acc[2][8][4];
#pragma unroll
    for (int a = 0; a < 2; a++)
#pragma unroll
        for (int b = 0; b < 8; b++)
#pragma unroll
            for (int q = 0; q < 4; q++) acc[a][b][q] = 0.f;

    const int nk = K >> 6;
    load_tile(0);
    load_tile(1);

    int a_row = wm * 32 + (seg & 1) * 8 + lr;
    int a_col = (seg >> 1) * 8;
    int b_row = wn * 64 + (seg >> 1) * 8 + lr;
    int b_col = (seg & 1) * 8;

    for (int c = 0; c < nk; c++) {
        if (c + 1 < nk) cp_wait<1>(); else cp_wait<0>();
        __syncthreads();
        if (c + 2 < nk) load_tile(c + 2);

        uint32_t aBase = sbase + (uint32_t)((c % NSTAGE) * 2 * TILEH) * 2;
        uint32_t bBase = aBase + (uint32_t)TILEH * 2;

#pragma unroll
        for (int s = 0; s < 4; s++) {
            uint32_t af[2][4], bf[8][2];
#pragma unroll
            for (int mt = 0; mt < 2; mt++)
                ldm_x4(af[mt], aBase + (uint32_t)((a_row + mt * 16) * KPADH + a_col + s * 16) * 2);
#pragma unroll
            for (int p = 0; p < 4; p++) {
                uint32_t r[4];
                ldm_x4(r, bBase + (uint32_t)((b_row + p * 16) * KPADH + b_col + s * 16) * 2);
                bf[2 * p][0]     = r[0];
                bf[2 * p][1]     = r[1];
                bf[2 * p + 1][0] = r[2];
                bf[2 * p + 1][1] = r[3];
            }
#pragma unroll
            for (int mt = 0; mt < 2; mt++)
#pragma unroll
                for (int nt = 0; nt < 8; nt++)
                    mma_f16(acc[mt][nt], af[mt], bf[nt]);
        }
    }

    // ---------------- epilogue ----------------
#pragma unroll
    for (int mt = 0; mt < 2; mt++) {
        int m0 = bm + wm * 32 + mt * 16 + g;
#pragma unroll
        for (int half = 0; half < 2; half++) {
            int m = m0 + half * 8;
            int batch = m >> 9;
#pragma unroll
            for (int nt = 0; nt < 8; nt++) {
                int n = bn + wn * 64 + nt * 8 + t * 2;
                float v0 = acc[mt][nt][half * 2 + 0] + bia[n];
                float v1 = acc[mt][nt][half * 2 + 1] + bia[n + 1];
                if (EPI == GEPI_GELU) {
                    float o0 = v0 * 0.5f * (1.0f + erff(v0 * 0.7071067811865475f));
                    float o1 = v1 * 0.5f * (1.0f + erff(v1 * 0.7071067811865475f));
                    *(__half2*)((__half*)Cv + (size_t)m * N + n) = __floats2half2_rn(o0, o1);
                } else if (EPI == GEPI_TANH) {
                    *(__half2*)((__half*)Cv + (size_t)m * N + n) = __floats2half2_rn(tanhf(v0), tanhf(v1));
                } else if (EPI == GEPI_BIAS) {
                    *(float2*)((float*)Cv + (size_t)m * N + n) = make_float2(v0, v1);
                } else {
                    float* C = (float*)Cv;
                    const float* gp = gate + (size_t)ii * N;
                    float tg0 = 1.f / (1.f + expf(-gp[n]));
                    float tg1 = 1.f / (1.f + expf(-gp[n + 1]));
                    float s0 = meanOther[(size_t)batch * Dsz + n] * 0.3f;
                    float s1 = meanOther[(size_t)batch * Dsz + n + 1] * 0.3f;
                    float h0 = v0 * (1.f + tg0 * torsion[n])     + s0 * tg0;
                    float h1 = v1 * (1.f + tg1 * torsion[n + 1]) + s1 * tg1;
                    float2 old = *(const float2*)(oldC + (size_t)m * N + n);
                    float o0 = old.x + 0.5f * h0, o1 = old.y + 0.5f * h1;
                    *(float2*)(C + (size_t)m * N + n) = make_float2(o0, o1);
                    if (mirror)
                        *(__half2*)(mirror + (size_t)m * N + n) = __floats2half2_rn(o0, o1);
                    if (outDup)
                        *(float2*)(outDup + (size_t)m * N + n) = make_float2(o0, o1);
                }
            }
        }
    }
}

// ---------------- host orchestration (2 streams, 5 events; A = high priority) ----------------
static cudaStream_t s_sA = nullptr, s_sB = nullptr;
static cudaEvent_t  s_eF = nullptr, s_eAm = nullptr, s_eBm = nullptr, s_eAf = nullptr, s_eBf = nullptr;
static void ensure_streams() {
    if (!s_sA) {
        int leastP = 0, greatestP = 0;
        cudaDeviceGetStreamPriorityRange(&leastP, &greatestP);
        cudaStreamCreateWithPriority(&s_sA, cudaStreamNonBlocking, greatestP);
        cudaStreamCreateWithPriority(&s_sB, cudaStreamNonBlocking, leastP);
        cudaEventCreateWithFlags(&s_eF,  cudaEventDisableTiming);
        cudaEventCreateWithFlags(&s_eAm, cudaEventDisableTiming);
        cudaEventCreateWithFlags(&s_eBm, cudaEventDisableTiming);
        cudaEventCreateWithFlags(&s_eAf, cudaEventDisableTiming);
        cudaEventCreateWithFlags(&s_eBf, cudaEventDisableTiming);
    }
}

extern "C" void kernel_launch(void* const* d_in, const int* in_sizes, int n_in,
                              void* d_out, int out_size) {
    const float* in_c   = (const float*)d_in[0];
    const float* in_b   = (const float*)d_in[1];
    const float* tors   = (const float*)d_in[2];
    const float* wsel_c = (const float*)d_in[3];
    const float* bsel_c = (const float*)d_in[4];
    const float* wsel_b = (const float*)d_in[5];
    const float* bsel_b = (const float*)d_in[6];
    const float* clng   = (const float*)d_in[7];
    const float* clnb   = (const float*)d_in[8];
    const float* cw1    = (const float*)d_in[9];
    const float* cb1    = (const float*)d_in[10];
    const float* cw2    = (const float*)d_in[11];
    const float* cb2    = (const float*)d_in[12];
    const float* cg     = (const float*)d_in[13];
    const float* blng   = (const float*)d_in[14];
    const float* blnb   = (const float*)d_in[15];
    const float* bw1    = (const float*)d_in[16];
    const float* bb1    = (const float*)d_in[17];
    const float* bw2    = (const float*)d_in[18];
    const float* bb2    = (const float*)d_in[19];
    const float* bg     = (const float*)d_in[20];
    const float* wcr    = (const float*)d_in[21];
    const float* bcr    = (const float*)d_in[22];
    float* out = (float*)d_out;

    ensure_streams();

    float *pc, *pb, *pmc, *pmb, *ppc, *ppb;
    __half *pxnc, *pxnb, *ph1c, *ph1b, *pcm, *pbm;
    __half *pcw1T, *pcw2T, *pbw1T, *pbw2T, *pwcrT;
    int *ptc, *ptb;
    cudaGetSymbolAddress((void**)&pc,   g_c);
    cudaGetSymbolAddress((void**)&pb,   g_b);
    cudaGetSymbolAddress((void**)&pxnc, g_xnh_c);
    cudaGetSymbolAddress((void**)&pxnb, g_xnh_b);
    cudaGetSymbolAddress((void**)&ph1c, g_h1h_c);
    cudaGetSymbolAddress((void**)&ph1b, g_h1h_b);
    cudaGetSymbolAddress((void**)&pcm,  g_cmir);
    cudaGetSymbolAddress((void**)&pbm,  g_bmir);
    cudaGetSymbolAddress((void**)&pmc,  g_mean_c);
    cudaGetSymbolAddress((void**)&pmb,  g_mean_b);
    cudaGetSymbolAddress((void**)&ppc,  g_part_c);
    cudaGetSymbolAddress((void**)&ppb,  g_part_b);
    cudaGetSymbolAddress((void**)&ptc,  g_top_c);
    cudaGetSymbolAddress((void**)&ptb,  g_top_b);
    cudaGetSymbolAddress((void**)&pcw1T, g_cw1T);
    cudaGetSymbolAddress((void**)&pcw2T, g_cw2T);
    cudaGetSymbolAddress((void**)&pbw1T, g_bw1T);
    cudaGetSymbolAddress((void**)&pbw2T, g_bw2T);
    cudaGetSymbolAddress((void**)&pwcrT, g_wcrT);

    cudaFuncSetAttribute(mma_gemm<GEPI_GELU,  false>, cudaFuncAttributeMaxDynamicSharedMemorySize, MMA_SMEM_BYTES);
    cudaFuncSetAttribute(mma_gemm<GEPI_TANH,  false>, cudaFuncAttributeMaxDynamicSharedMemorySize, MMA_SMEM_BYTES);
    cudaFuncSetAttribute(mma_gemm<GEPI_BLOCK, false>, cudaFuncAttributeMaxDynamicSharedMemorySize, MMA_SMEM_BYTES);
    cudaFuncSetAttribute(mma_gemm<GEPI_BIAS,  true >, cudaFuncAttributeMaxDynamicSharedMemorySize, MMA_SMEM_BYTES);

    dim3 tb(32, 8);
    dim3 gN4(4, Msz / 128);
    dim3 gN8(8, Msz / 128);

    // ---- fork immediately; layer 0 reads inputs in place ----
    cudaEventRecord(s_eF, 0);
    cudaStreamWaitEvent(s_sA, s_eF, 0);
    cudaStreamWaitEvent(s_sB, s_eF, 0);
    transpose_h_kernel<<<dim3(16, 32, 1), tb>>>(wcr + (size_t)3 * 1024 * 512, pwcrT, 1024, 512, nullptr);

    for (int l = 0; l < LNUM; l++) {
        int par = l & 1;
        float* mcl = pmc + (size_t)par * Bsz * Dsz;
        float* mbl = pmb + (size_t)par * Bsz * Dsz;
        const float* srcC = (l == 0) ? in_c : pc;
        const float* srcB = (l == 0) ? in_b : pb;

        // ---- stream A head: partial -> finish(+route) -> fused{transpose, LN j0} ----
        colmean_partial_kernel<<<dim3(Bsz, NCHUNK), 512, 0, s_sA>>>(srcC, ppc);
        colmean_finish_route_kernel<<<Bsz, 512, 0, s_sA>>>(ppc, mcl,
            wsel_c + (size_t)l * Dsz * NB, bsel_c + l * NB, ptc);
        cudaEventRecord(s_eAm, s_sA);
        head_ln_trans_kernel<<<4096 + Msz / 8, 256, 0, s_sA>>>(
            cw1 + (size_t)l * NB * 512 * 1024, pcw1T + (size_t)l * NB * 1024 * 512, 512, 1024,
            cw2 + (size_t)l * NB * 1024 * 512, pcw2T + (size_t)l * NB * 512 * 1024, 1024, 512,
            ptc, 4096, 32, 32,
            srcC, pxnc, clng + (size_t)l * NB * Dsz, clnb + (size_t)l * NB * Dsz);

        // ---- stream B head ----
        colmean_partial_kernel<<<dim3(Bsz, NCHUNK), 512, 0, s_sB>>>(srcB, ppb);
        colmean_finish_route_kernel<<<Bsz, 512, 0, s_sB>>>(ppb, mbl,
            wsel_b + (size_t)l * Dsz * NB, bsel_b + l * NB, ptb);
        cudaEventRecord(s_eBm, s_sB);
        head_ln_trans_kernel<<<1024 + Msz / 8, 256, 0, s_sB>>>(
            bw1 + (size_t)l * NB * 512 * 512, pbw1T + (size_t)l * NB * 512 * 512, 512, 512,
            bw2 + (size_t)l * NB * 512 * 512, pbw2T + (size_t)l * NB * 512 * 512, 512, 512,
            ptb, 1024, 16, 16,
            srcB, pxnb, blng + (size_t)l * NB * Dsz, blnb + (size_t)l * NB * Dsz);

        bool last = (l == LNUM - 1);
        __half* cmir = last ? pcm : nullptr;
        __half* bmir = last ? pbm : nullptr;

        // ---- stream A: cortical blocks ----
        for (int j = 0; j < 2; j++) {
            const float* stC = (l == 0 && j == 0) ? in_c : pc;
            if (j == 1)  // LN j=1 depends on G2 j=0's state update
                ln_kernel<<<Msz / 8, 256, 0, s_sA>>>(pc, pxnc, clng + (size_t)l * NB * Dsz,
                                                     clnb + (size_t)l * NB * Dsz, ptc, 1);
            mma_gemm<GEPI_GELU, false><<<gN8, 256, MMA_SMEM_BYTES, s_sA>>>(
                pxnc, nullptr, pcw1T + (size_t)l * NB * 1024 * 512,
                cb1 + (size_t)l * NB * 1024, ph1c, nullptr, nullptr, nullptr, Msz, 1024, 512,
                nullptr, nullptr, nullptr, ptc, j);
            if (j == 0) cudaStreamWaitEvent(s_sA, s_eBm, 0);
            mma_gemm<GEPI_BLOCK, false><<<gN4, 256, MMA_SMEM_BYTES, s_sA>>>(
                ph1c, nullptr, pcw2T + (size_t)l * NB * 512 * 1024,
                cb2 + (size_t)l * NB * 512, pc, stC, cmir,
                (last && j == 1) ? out : nullptr, Msz, 512, 1024,
                cg + (size_t)l * NB * Dsz, tors, mbl, ptc, j);
        }
        // ---- stream B: brainstem blocks ----
        for (int j = 0; j < 2; j++) {
            const float* stB = (l == 0 && j == 0) ? in_b : pb;
            if (j == 1)
                ln_kernel<<<Msz / 8, 256, 0, s_sB>>>(pb, pxnb, blng + (size_t)l * NB * Dsz,
                                                     blnb + (size_t)l * NB * Dsz, ptb, 1);
            mma_gemm<GEPI_TANH, false><<<gN4, 256, MMA_SMEM_BYTES, s_sB>>>(
                pxnb, nullptr, pbw1T + (size_t)l * NB * 512 * 512,
                bb1 + (size_t)l * NB * 512, ph1b, nullptr, nullptr, nullptr, Msz, 512, 512,
                nullptr, nullptr, nullptr, ptb, j);
            if (j == 0) cudaStreamWaitEvent(s_sB, s_eAm, 0);
            mma_gemm<GEPI_BLOCK, false><<<gN4, 256, MMA_SMEM_BYTES, s_sB>>>(
                ph1b, nullptr, pbw2T + (size_t)l * NB * 512 * 512,
                bb2 + (size_t)l * NB * 512, pb, stB, bmir,
                (last && j == 1) ? (out + BSD) : nullptr, Msz, 512, 512,
                bg + (size_t)l * NB * Dsz, tors, mcl, ptb, j);
        }
    }

    // states already dual-written into out by the last-layer G2 epilogues; just join + cross GEMM
    cudaEventRecord(s_eAf, s_sA);
    cudaEventRecord(s_eBf, s_sB);
    cudaStreamWaitEvent(0, s_eAf, 0);
    cudaStreamWaitEvent(0, s_eBf, 0);
    mma_gemm<GEPI_BIAS, true><<<gN4, 256, MMA_SMEM_BYTES>>>(
        pcm, pbm, pwcrT, bcr + (size_t)3 * Dsz,
        out + 2 * (size_t)BSD, nullptr, nullptr, nullptr, Msz, 512, 1024,
        nullptr, nullptr, nullptr, nullptr, 0);
}

// round 16
// speedup vs baseline: 1.0082x; 1.0082x over previous
#include <cuda_runtime.h>
#include <cuda_fp16.h>
#include <math.h>
#include <stdint.h>

// Problem constants
#define LNUM 4
#define NB   8
#define Bsz  16
#define Ssz  512
#define Dsz  512
#define Msz  (Bsz * Ssz)          // 8192
#define BSD  (Bsz * Ssz * Dsz)

#define NCHUNK 32
#define ROWS_PER_CHUNK (Ssz / NCHUNK)   // 16

// ---------------- device scratch ----------------
__device__ float  g_c[BSD];
__device__ float  g_b[BSD];
__device__ __half g_xnh_c[BSD];
__device__ __half g_xnh_b[BSD];
__device__ __half g_h1h_c[Bsz * Ssz * 2 * Dsz];
__device__ __half g_h1h_b[BSD];
__device__ __half g_cmir[BSD];
__device__ __half g_bmir[BSD];
__device__ float  g_mean_c[2 * Bsz * Dsz];
__device__ float  g_mean_b[2 * Bsz * Dsz];
__device__ float  g_part_c[Bsz * NCHUNK * Dsz];
__device__ float  g_part_b[Bsz * NCHUNK * Dsz];
__device__ int    g_top_c[2];
__device__ int    g_top_b[2];
__device__ __half g_cw1T[4 * 8 * 1024 * 512];
__device__ __half g_cw2T[4 * 8 * 512 * 1024];
__device__ __half g_bw1T[4 * 8 * 512 * 512];
__device__ __half g_bw2T[4 * 8 * 512 * 512];
__device__ __half g_wcrT[512 * 1024];

// ---------------- helpers ----------------
__device__ __forceinline__ uint32_t smem_u32(const void* p) {
    uint32_t a;
    asm("{ .reg .u64 t; cvta.to.shared.u64 t, %1; cvt.u32.u64 %0, t; }" : "=r"(a) : "l"(p));
    return a;
}
__device__ __forceinline__ void cp_async16(uint32_t saddr, const void* gaddr) {
    asm volatile("cp.async.cg.shared.global [%0], [%1], 16;" :: "r"(saddr), "l"(gaddr) : "memory");
}
__device__ __forceinline__ void cp_commit() {
    asm volatile("cp.async.commit_group;" ::: "memory");
}
template <int N>
__device__ __forceinline__ void cp_wait() {
    asm volatile("cp.async.wait_group %0;" :: "n"(N) : "memory");
}
__device__ __forceinline__ void ldm_x4(uint32_t* r, uint32_t addr) {
    asm volatile("ldmatrix.sync.aligned.m8n8.x4.shared.b16 {%0,%1,%2,%3}, [%4];"
        : "=r"(r[0]), "=r"(r[1]), "=r"(r[2]), "=r"(r[3]) : "r"(addr));
}
__device__ __forceinline__ void mma_f16(float* c, const uint32_t* a, const uint32_t* b) {
    asm volatile(
        "mma.sync.aligned.m16n8k16.row.col.f32.f16.f16.f32 "
        "{%0,%1,%2,%3}, {%4,%5,%6,%7}, {%8,%9}, {%0,%1,%2,%3};"
        : "+f"(c[0]), "+f"(c[1]), "+f"(c[2]), "+f"(c[3])
        : "r"(a[0]), "r"(a[1]), "r"(a[2]), "r"(a[3]), "r"(b[0]), "r"(b[1]));
}
__device__ __forceinline__ float warp_sum(float v) {
#pragma unroll
    for (int o = 16; o > 0; o >>= 1) v += __shfl_xor_sync(0xffffffffu, v, o);
    return v;
}

// ---------------- small kernels ----------------
__global__ void colmean_partial_kernel(const float* __restrict__ x, float* __restrict__ part) {
    int b = blockIdx.x;
    int s = blockIdx.y;
    int d = threadIdx.x;
    const float* p = x + ((size_t)b * Ssz + (size_t)s * ROWS_PER_CHUNK) * Dsz + d;
    float sum = 0.f;
#pragma unroll
    for (int t = 0; t < ROWS_PER_CHUNK; t++) sum += p[(size_t)t * Dsz];
    part[((size_t)b * NCHUNK + s) * Dsz + d] = sum;
}

__global__ void colmean_finish_route_kernel(const float* __restrict__ part,
                                            float* __restrict__ mean,
                                            const float* __restrict__ wsel,
                                            const float* __restrict__ bsel,
                                            int* __restrict__ top) {
    __shared__ float smean[Dsz];
    __shared__ float adj[NB];
    int b = blockIdx.x;
    int d = threadIdx.x;
    const float* pp = part + (size_t)b * NCHUNK * Dsz + d;
    float s = 0.f;
#pragma unroll
    for (int t = 0; t < NCHUNK; t++) s += pp[(size_t)t * Dsz];
    float m = s * (1.0f / Ssz);
    mean[b * Dsz + d] = m;
    if (b == 0) {
        smean[d] = m;
        __syncthreads();
        if (d < 256) {
            int lane = d & 31, w = d >> 5;
            float acc = 0.f;
            for (int k = lane; k < Dsz; k += 32) acc += smean[k] * wsel[k * NB + w];
#pragma unroll
            for (int o = 16; o > 0; o >>= 1) acc += __shfl_down_sync(0xffffffffu, acc, o);
            if (lane == 0) {
                float sc = 1.f / (1.f + expf(-(acc + bsel[w])));
                adj[w] = sc * 0.7f + 0.15f;
            }
        }
        __syncthreads();
        if (d == 0) {
            int i1 = 0; float v1 = adj[0];
            for (int n = 1; n < NB; n++) if (adj[n] > v1) { v1 = adj[n]; i1 = n; }
            int i2 = -1; float v2 = -1e30f;
            for (int n = 0; n < NB; n++) if (n != i1 && adj[n] > v2) { v2 = adj[n]; i2 = n; }
            top[0] = i1; top[1] = i2;
        }
    }
}

__global__ void ln_kernel(const float* __restrict__ x, __half* __restrict__ xn,
                          const float* __restrict__ lng, const float* __restrict__ lnb,
                          const int* __restrict__ top, int jsel) {
    int i = top[jsel];
    int row = blockIdx.x * 8 + (threadIdx.x >> 5);
    int lane = threadIdx.x & 31;
    const float4* xr = (const float4*)(x + (size_t)row * Dsz);
    float4 v[4];
    float s = 0.f;
#pragma unroll
    for (int q = 0; q < 4; q++) {
        v[q] = xr[lane + q * 32];
        s += v[q].x + v[q].y + v[q].z + v[q].w;
    }
    float mu = warp_sum(s) * (1.f / Dsz);
    float ss = 0.f;
#pragma unroll
    for (int q = 0; q < 4; q++) {
        float a = v[q].x - mu, b = v[q].y - mu, c = v[q].z - mu, d = v[q].w - mu;
        ss += a * a + b * b + c * c + d * d;
    }
    float r = rsqrtf(warp_sum(ss) * (1.f / Dsz) + 1e-5f);
    const float4* gg = (const float4*)(lng + (size_t)i * Dsz);
    const float4* bb = (const float4*)(lnb + (size_t)i * Dsz);
#pragma unroll
    for (int q = 0; q < 4; q++) {
        int c4 = lane + q * 32;
        float4 g = gg[c4], be = bb[c4];
        float o0 = (v[q].x - mu) * r * g.x + be.x;
        float o1 = (v[q].y - mu) * r * g.y + be.y;
        float o2 = (v[q].z - mu) * r * g.z + be.z;
        float o3 = (v[q].w - mu) * r * g.w + be.w;
        __half2 h0 = __floats2half2_rn(o0, o1);
        __half2 h1 = __floats2half2_rn(o2, o3);
        uint2 pk = make_uint2(*(uint32_t*)&h0, *(uint32_t*)&h1);
        *(uint2*)(xn + (size_t)row * Dsz + c4 * 4) = pk;
    }
}

__global__ void transpose_h_kernel(const float* __restrict__ W, __half* __restrict__ WT,
                                   int K, int N, const int* __restrict__ top) {
    __shared__ float tile[32][33];
    int ii = top ? top[blockIdx.z] : (int)blockIdx.z;
    const float* Wz = W + (size_t)ii * K * N;
    __half* Tz = WT + (size_t)ii * K * N;
    int x = blockIdx.x * 32 + threadIdx.x;
    int y0 = blockIdx.y * 32;
#pragma unroll
    for (int j = 0; j < 4; j++)
        tile[threadIdx.y + j * 8][threadIdx.x] = Wz[(size_t)(y0 + threadIdx.y + j * 8) * N + x];
    __syncthreads();
    int x2 = blockIdx.y * 32 + threadIdx.x;
    int y2 = blockIdx.x * 32;
#pragma unroll
    for (int j = 0; j < 4; j++)
        Tz[(size_t)(y2 + threadIdx.y + j * 8) * K + x2] = __float2half_rn(tile[threadIdx.x][threadIdx.y + j * 8]);
}

__global__ void transpose2_h_kernel(const float* __restrict__ W1, __half* __restrict__ WT1,
                                    int K1, int N1,
                                    const float* __restrict__ W2, __half* __restrict__ WT2,
                                    int K2, int N2,
                                    const int* __restrict__ top) {
    __shared__ float tile[32][33];
    int msel = blockIdx.z >> 1, blk = blockIdx.z & 1;
    const float* W = msel ? W2 : W1;
    __half* WT = msel ? WT2 : WT1;
    int K = msel ? K2 : K1, N = msel ? N2 : N1;
    if ((int)blockIdx.x * 32 >= N || (int)blockIdx.y * 32 >= K) return;
    int ii = top[blk];
    const float* Wz = W + (size_t)ii * K * N;
    __half* Tz = WT + (size_t)ii * K * N;
    int x = blockIdx.x * 32 + threadIdx.x;
    int y0 = blockIdx.y * 32;
#pragma unroll
    for (int j = 0; j < 4; j++)
        tile[threadIdx.y + j * 8][threadIdx.x] = Wz[(size_t)(y0 + threadIdx.y + j * 8) * N + x];
    __syncthreads();
    int x2 = blockIdx.y * 32 + threadIdx.x;
    int y2 = blockIdx.x * 32;
#pragma unroll
    for (int j = 0; j < 4; j++)
        Tz[(size_t)(y2 + threadIdx.y + j * 8) * K + x2] = __float2half_rn(tile[threadIdx.x][threadIdx.y + j * 8]);
}

// ---------------- fp16 mma.sync GEMM: 128x128 tile, BK=64, 3-stage, single barrier ----------------
#define GEPI_GELU  0
#define GEPI_TANH  1
#define GEPI_BLOCK 2
#define GEPI_BIAS  3

#define KPADH 72
#define TILEH (128 * KPADH)
#define NSTAGE 3
#define MMA_SMEM_BYTES (NSTAGE * 2 * TILEH * 2)   // 110592 B

template <int EPI, bool CONCAT>
__global__ void __launch_bounds__(256, 2) mma_gemm(
    const __half* __restrict__ A, const __half* __restrict__ A2,
    const __half* __restrict__ BT, const float* __restrict__ bias,
    void* __restrict__ Cv, const float* __restrict__ oldC,
    __half* __restrict__ mirror, float* __restrict__ outDup,
    int M, int N, int K,
    const float* __restrict__ gate, const float* __restrict__ torsion,
    const float* __restrict__ meanOther,
    const int* __restrict__ top, int jsel)
{
    extern __shared__ __half smh[];

    int tid = threadIdx.x;
    int wid = tid >> 5, lane = tid & 31;
    int g = lane >> 2, t = lane & 3;
    int lr = lane & 7, seg = lane >> 3;
    int wm = wid & 3, wn = wid >> 2;
    int bm = blockIdx.y * 128;
    int bn = blockIdx.x * 128;

    int ii = 0;
    if (top) ii = top[jsel];
    const __half* Bp  = BT + (size_t)ii * K * N + (size_t)bn * K;
    const float*  bia = bias + (size_t)ii * N;

    uint32_t sbase = smem_u32(smh);

    auto load_tile = [&](int c) {
        int st = c % NSTAGE;
        int k0 = c << 6;
        uint32_t sAa = sbase + (uint32_t)(st * 2 * TILEH) * 2;
        uint32_t sBa = sAa + (uint32_t)TILEH * 2;
#pragma unroll
        for (int i = 0; i < 4; i++) {
            int idx = i * 256 + tid;
            int row = idx >> 3;
            int ch  = (idx & 7) * 8;
            const __half* gsrc;
            if (CONCAT) {
                int kk = k0 + ch;
                gsrc = (kk < 512) ? (A + (size_t)(bm + row) * 512 + kk)
                                  : (A2 + (size_t)(bm + row) * 512 + (kk - 512));
            } else {
                gsrc = A + (size_t)(bm + row) * K + k0 + ch;
            }
            cp_async16(sAa + (uint32_t)(row * KPADH + ch) * 2, gsrc);
            cp_async16(sBa + (uint32_t)(row * KPADH + ch) * 2, Bp + (size_t)row * K + k0 + ch);
        }
        cp_commit();
    };

    float acc[2][8][4];
#pragma unroll
    for (int a = 0; a < 2; a++)
#pragma unroll
        for (int b = 0; b < 8; b++)
#pragma unroll
            for (int q = 0; q < 4; q++) acc[a][b][q] = 0.f;

    const int nk = K >> 6;
    load_tile(0);
    load_tile(1);

    int a_row = wm * 32 + (seg & 1) * 8 + lr;
    int a_col = (seg >> 1) * 8;
    int b_row = wn * 64 + (seg >> 1) * 8 + lr;
    int b_col = (seg & 1) * 8;

    for (int c = 0; c < nk; c++) {
        if (c + 1 < nk) cp_wait<1>(); else cp_wait<0>();
        __syncthreads();
        if (c + 2 < nk) load_tile(c + 2);

        uint32_t aBase = sbase + (uint32_t)((c % NSTAGE) * 2 * TILEH) * 2;
        uint32_t bBase = aBase + (uint32_t)TILEH * 2;

#pragma unroll
        for (int s = 0; s < 4; s++) {
            uint32_t af[2][4], bf[8][2];
#pragma unroll
            for (int mt = 0; mt < 2; mt++)
                ldm_x4(af[mt], aBase + (uint32_t)((a_row + mt * 16) * KPADH + a_col + s * 16) * 2);
#pragma unroll
            for (int p = 0; p < 4; p++) {
                uint32_t r[4];
                ldm_x4(r, bBase + (uint32_t)((b_row + p * 16) * KPADH + b_col + s * 16) * 2);
                bf[2 * p][0]     = r[0];
                bf[2 * p][1]     = r[1];
                bf[2 * p + 1][0] = r[2];
                bf[2 * p + 1][1] = r[3];
            }
#pragma unroll
            for (int mt = 0; mt < 2; mt++)
#pragma unroll
                for (int nt = 0; nt < 8; nt++)
                    mma_f16(acc[mt][nt], af[mt], bf[nt]);
        }
    }

    // ---------------- epilogue ----------------
#pragma unroll
    for (int mt = 0; mt < 2; mt++) {
        int m0 = bm + wm * 32 + mt * 16 + g;
#pragma unroll
        for (int half = 0; half < 2; half++) {
            int m = m0 + half * 8;
            int batch = m >> 9;
#pragma unroll
            for (int nt = 0; nt < 8; nt++) {
                int n = bn + wn * 64 + nt * 8 + t * 2;
                float v0 = acc[mt][nt][half * 2 + 0] + bia[n];
                float v1 = acc[mt][nt][half * 2 + 1] + bia[n + 1];
                if (EPI == GEPI_GELU) {
                    float o0 = v0 * 0.5f * (1.0f + erff(v0 * 0.7071067811865475f));
                    float o1 = v1 * 0.5f * (1.0f + erff(v1 * 0.7071067811865475f));
                    *(__half2*)((__half*)Cv + (size_t)m * N + n) = __floats2half2_rn(o0, o1);
                } else if (EPI == GEPI_TANH) {
                    *(__half2*)((__half*)Cv + (size_t)m * N + n) = __floats2half2_rn(tanhf(v0), tanhf(v1));
                } else if (EPI == GEPI_BIAS) {
                    *(float2*)((float*)Cv + (size_t)m * N + n) = make_float2(v0, v1);
                } else {
                    float* C = (float*)Cv;
                    const float* gp = gate + (size_t)ii * N;
                    float tg0 = 1.f / (1.f + expf(-gp[n]));
                    float tg1 = 1.f / (1.f + expf(-gp[n + 1]));
                    float s0 = meanOther[(size_t)batch * Dsz + n] * 0.3f;
                    float s1 = meanOther[(size_t)batch * Dsz + n + 1] * 0.3f;
                    float h0 = v0 * (1.f + tg0 * torsion[n])     + s0 * tg0;
                    float h1 = v1 * (1.f + tg1 * torsion[n + 1]) + s1 * tg1;
                    float2 old = *(const float2*)(oldC + (size_t)m * N + n);
                    float o0 = old.x + 0.5f * h0, o1 = old.y + 0.5f * h1;
                    *(float2*)(C + (size_t)m * N + n) = make_float2(o0, o1);
                    if (mirror)
                        *(__half2*)(mirror + (size_t)m * N + n) = __floats2half2_rn(o0, o1);
                    if (outDup)
                        *(float2*)(outDup + (size_t)m * N + n) = make_float2(o0, o1);
                }
            }
        }
    }
}

// ---------------- host orchestration (2 streams, 5 events; A = high priority) ----------------
static cudaStream_t s_sA = nullptr, s_sB = nullptr;
static cudaEvent_t  s_eF = nullptr, s_eAm = nullptr, s_eBm = nullptr, s_eAf = nullptr, s_eBf = nullptr;
static void ensure_streams() {
    if (!s_sA) {
        int leastP = 0, greatestP = 0;
        cudaDeviceGetStreamPriorityRange(&leastP, &greatestP);
        cudaStreamCreateWithPriority(&s_sA, cudaStreamNonBlocking, greatestP);
        cudaStreamCreateWithPriority(&s_sB, cudaStreamNonBlocking, leastP);
        cudaEventCreateWithFlags(&s_eF,  cudaEventDisableTiming);
        cudaEventCreateWithFlags(&s_eAm, cudaEventDisableTiming);
        cudaEventCreateWithFlags(&s_eBm, cudaEventDisableTiming);
        cudaEventCreateWithFlags(&s_eAf, cudaEventDisableTiming);
        cudaEventCreateWithFlags(&s_eBf, cudaEventDisableTiming);
    }
}

extern "C" void kernel_launch(void* const* d_in, const int* in_sizes, int n_in,
                              void* d_out, int out_size) {
    const float* in_c   = (const float*)d_in[0];
    const float* in_b   = (const float*)d_in[1];
    const float* tors   = (const float*)d_in[2];
    const float* wsel_c = (const float*)d_in[3];
    const float* bsel_c = (const float*)d_in[4];
    const float* wsel_b = (const float*)d_in[5];
    const float* bsel_b = (const float*)d_in[6];
    const float* clng   = (const float*)d_in[7];
    const float* clnb   = (const float*)d_in[8];
    const float* cw1    = (const float*)d_in[9];
    const float* cb1    = (const float*)d_in[10];
    const float* cw2    = (const float*)d_in[11];
    const float* cb2    = (const float*)d_in[12];
    const float* cg     = (const float*)d_in[13];
    const float* blng   = (const float*)d_in[14];
    const float* blnb   = (const float*)d_in[15];
    const float* bw1    = (const float*)d_in[16];
    const float* bb1    = (const float*)d_in[17];
    const float* bw2    = (const float*)d_in[18];
    const float* bb2    = (const float*)d_in[19];
    const float* bg     = (const float*)d_in[20];
    const float* wcr    = (const float*)d_in[21];
    const float* bcr    = (const float*)d_in[22];
    float* out = (float*)d_out;

    ensure_streams();

    float *pc, *pb, *pmc, *pmb, *ppc, *ppb;
    __half *pxnc, *pxnb, *ph1c, *ph1b, *pcm, *pbm;
    __half *pcw1T, *pcw2T, *pbw1T, *pbw2T, *pwcrT;
    int *ptc, *ptb;
    cudaGetSymbolAddress((void**)&pc,   g_c);
    cudaGetSymbolAddress((void**)&pb,   g_b);
    cudaGetSymbolAddress((void**)&pxnc, g_xnh_c);
    cudaGetSymbolAddress((void**)&pxnb, g_xnh_b);
    cudaGetSymbolAddress((void**)&ph1c, g_h1h_c);
    cudaGetSymbolAddress((void**)&ph1b, g_h1h_b);
    cudaGetSymbolAddress((void**)&pcm,  g_cmir);
    cudaGetSymbolAddress((void**)&pbm,  g_bmir);
    cudaGetSymbolAddress((void**)&pmc,  g_mean_c);
    cudaGetSymbolAddress((void**)&pmb,  g_mean_b);
    cudaGetSymbolAddress((void**)&ppc,  g_part_c);
    cudaGetSymbolAddress((void**)&ppb,  g_part_b);
    cudaGetSymbolAddress((void**)&ptc,  g_top_c);
    cudaGetSymbolAddress((void**)&ptb,  g_top_b);
    cudaGetSymbolAddress((void**)&pcw1T, g_cw1T);
    cudaGetSymbolAddress((void**)&pcw2T, g_cw2T);
    cudaGetSymbolAddress((void**)&pbw1T, g_bw1T);
    cudaGetSymbolAddress((void**)&pbw2T, g_bw2T);
    cudaGetSymbolAddress((void**)&pwcrT, g_wcrT);

    cudaFuncSetAttribute(mma_gemm<GEPI_GELU,  false>, cudaFuncAttributeMaxDynamicSharedMemorySize, MMA_SMEM_BYTES);
    cudaFuncSetAttribute(mma_gemm<GEPI_TANH,  false>, cudaFuncAttributeMaxDynamicSharedMemorySize, MMA_SMEM_BYTES);
    cudaFuncSetAttribute(mma_gemm<GEPI_BLOCK, false>, cudaFuncAttributeMaxDynamicSharedMemorySize, MMA_SMEM_BYTES);
    cudaFuncSetAttribute(mma_gemm<GEPI_BIAS,  true >, cudaFuncAttributeMaxDynamicSharedMemorySize, MMA_SMEM_BYTES);

    dim3 tb(32, 8);
    dim3 gN4(4, Msz / 128);
    dim3 gN8(8, Msz / 128);

    // ---- fork immediately; layer 0 reads inputs in place ----
    cudaEventRecord(s_eF, 0);
    cudaStreamWaitEvent(s_sA, s_eF, 0);
    cudaStreamWaitEvent(s_sB, s_eF, 0);
    transpose_h_kernel<<<dim3(16, 32, 1), tb>>>(wcr + (size_t)3 * 1024 * 512, pwcrT, 1024, 512, nullptr);

    for (int l = 0; l < LNUM; l++) {
        int par = l & 1;
        float* mcl = pmc + (size_t)par * Bsz * Dsz;
        float* mbl = pmb + (size_t)par * Bsz * Dsz;
        const float* srcC = (l == 0) ? in_c : pc;
        const float* srcB = (l == 0) ? in_b : pb;

        // ---- stream A head ----
        colmean_partial_kernel<<<dim3(Bsz, NCHUNK), 512, 0, s_sA>>>(srcC, ppc);
        colmean_finish_route_kernel<<<Bsz, 512, 0, s_sA>>>(ppc, mcl,
            wsel_c + (size_t)l * Dsz * NB, bsel_c + l * NB, ptc);
        cudaEventRecord(s_eAm, s_sA);
        transpose2_h_kernel<<<dim3(32, 32, 4), tb, 0, s_sA>>>(
            cw1 + (size_t)l * NB * 512 * 1024, pcw1T + (size_t)l * NB * 1024 * 512, 512, 1024,
            cw2 + (size_t)l * NB * 1024 * 512, pcw2T + (size_t)l * NB * 512 * 1024, 1024, 512, ptc);

        // ---- stream B head ----
        colmean_partial_kernel<<<dim3(Bsz, NCHUNK), 512, 0, s_sB>>>(srcB, ppb);
        colmean_finish_route_kernel<<<Bsz, 512, 0, s_sB>>>(ppb, mbl,
            wsel_b + (size_t)l * Dsz * NB, bsel_b + l * NB, ptb);
        cudaEventRecord(s_eBm, s_sB);
        transpose2_h_kernel<<<dim3(16, 16, 4), tb, 0, s_sB>>>(
            bw1 + (size_t)l * NB * 512 * 512, pbw1T + (size_t)l * NB * 512 * 512, 512, 512,
            bw2 + (size_t)l * NB * 512 * 512, pbw2T + (size_t)l * NB * 512 * 512, 512, 512, ptb);

        bool last = (l == LNUM - 1);
        __half* cmir = last ? pcm : nullptr;
        __half* bmir = last ? pbm : nullptr;

        // ---- stream A: cortical blocks ----
        for (int j = 0; j < 2; j++) {
            const float* stC = (l == 0 && j == 0) ? in_c : pc;
            ln_kernel<<<Msz / 8, 256, 0, s_sA>>>(stC, pxnc, clng + (size_t)l * NB * Dsz,
                                                 clnb + (size_t)l * NB * Dsz, ptc, j);
            mma_gemm<GEPI_GELU, false><<<gN8, 256, MMA_SMEM_BYTES, s_sA>>>(
                pxnc, nullptr, pcw1T + (size_t)l * NB * 1024 * 512,
                cb1 + (size_t)l * NB * 1024, ph1c, nullptr, nullptr, nullptr, Msz, 1024, 512,
                nullptr, nullptr, nullptr, ptc, j);
            if (j == 0) cudaStreamWaitEvent(s_sA, s_eBm, 0);
            mma_gemm<GEPI_BLOCK, false><<<gN4, 256, MMA_SMEM_BYTES, s_sA>>>(
                ph1c, nullptr, pcw2T + (size_t)l * NB * 512 * 1024,
                cb2 + (size_t)l * NB * 512, pc, stC, cmir,
                (last && j == 1) ? out : nullptr, Msz, 512, 1024,
                cg + (size_t)l * NB * Dsz, tors, mbl, ptc, j);
        }
        // ---- stream B: brainstem blocks ----
        for (int j = 0; j < 2; j++) {
            const float* stB = (l == 0 && j == 0) ? in_b : pb;
            ln_kernel<<<Msz / 8, 256, 0, s_sB>>>(stB, pxnb, blng + (size_t)l * NB * Dsz,
                                                 blnb + (size_t)l * NB * Dsz, ptb, j);
            mma_gemm<GEPI_TANH, false><<<gN4, 256, MMA_SMEM_BYTES, s_sB>>>(
                pxnb, nullptr, pbw1T + (size_t)l * NB * 512 * 512,
                bb1 + (size_t)l * NB * 512, ph1b, nullptr, nullptr, nullptr, Msz, 512, 512,
                nullptr, nullptr, nullptr, ptb, j);
            if (j == 0) cudaStreamWaitEvent(s_sB, s_eAm, 0);
            mma_gemm<GEPI_BLOCK, false><<<gN4, 256, MMA_SMEM_BYTES, s_sB>>>(
                ph1b, nullptr, pbw2T + (size_t)l * NB * 512 * 512,
                bb2 + (size_t)l * NB * 512, pb, stB, bmir,
                (last && j == 1) ? (out + BSD) : nullptr, Msz, 512, 512,
                bg + (size_t)l * NB * Dsz, tors, mcl, ptb, j);
        }
    }

    // states already dual-written into out by the last-layer G2 epilogues (outDup);
    // no final memcpys needed — just join + cross GEMM.
    cudaEventRecord(s_eAf, s_sA);
    cudaEventRecord(s_eBf, s_sB);
    cudaStreamWaitEvent(0, s_eAf, 0);
    cudaStreamWaitEvent(0, s_eBf, 0);
    mma_gemm<GEPI_BIAS, true><<<gN4, 256, MMA_SMEM_BYTES>>>(
        pcm, pbm, pwcrT, bcr + (size_t)3 * Dsz,
        out + 2 * (size_t)BSD, nullptr, nullptr, nullptr, Msz, 512, 1024,
        nullptr, nullptr, nullptr, nullptr, 0);
}